// round 1
// baseline (speedup 1.0000x reference)
#include <cuda_runtime.h>
#include <math.h>

#define BDIM 2
#define SEQ  2048
#define DMODEL 1024
#define NH   16
#define HD   64
#define MROWS (BDIM*SEQ)     // 4096
#define DFF  4096
#define LN_EPS 1e-9f

// ---------------- scratch (device globals; no allocation allowed) ----------------
__device__ float g_buf0[(size_t)MROWS*DMODEL];  // ln1 out, then attention O
__device__ float g_buf1[(size_t)MROWS*DMODEL];  // Q, then ln2 out
__device__ float g_buf2[(size_t)MROWS*DMODEL];  // K
__device__ float g_buf3[(size_t)MROWS*DMODEL];  // V
__device__ float g_buf4[(size_t)MROWS*DMODEL];  // y1 = x + attn
__device__ float g_mid [(size_t)MROWS*DFF];     // MLP mid (gelu)

// ---------------- LayerNorm (torch var: ddof=1), two-pass ----------------
__global__ __launch_bounds__(256) void ln_kernel(
    const float* __restrict__ x, const float* __restrict__ mean_scale,
    const float* __restrict__ std_scale, float* __restrict__ out)
{
    int row = blockIdx.x;
    int t = threadIdx.x;
    const float4* xr = (const float4*)(x + (size_t)row*DMODEL);
    float4 v = xr[t];

    __shared__ float red[8];
    float s = v.x + v.y + v.z + v.w;
    #pragma unroll
    for (int m = 16; m > 0; m >>= 1) s += __shfl_xor_sync(0xffffffffu, s, m);
    if ((t & 31) == 0) red[t >> 5] = s;
    __syncthreads();
    if (t < 8) {
        float r = red[t];
        #pragma unroll
        for (int m = 4; m > 0; m >>= 1) r += __shfl_xor_sync(0xffu, r, m);
        if (t == 0) red[0] = r;
    }
    __syncthreads();
    float mean = red[0] * (1.0f / DMODEL);
    float dx = v.x - mean, dy = v.y - mean, dz = v.z - mean, dw = v.w - mean;
    float q = dx*dx + dy*dy + dz*dz + dw*dw;
    __syncthreads();  // everyone has read red[0]
    #pragma unroll
    for (int m = 16; m > 0; m >>= 1) q += __shfl_xor_sync(0xffffffffu, q, m);
    if ((t & 31) == 0) red[t >> 5] = q;
    __syncthreads();
    if (t < 8) {
        float r = red[t];
        #pragma unroll
        for (int m = 4; m > 0; m >>= 1) r += __shfl_xor_sync(0xffu, r, m);
        if (t == 0) red[0] = r;
    }
    __syncthreads();
    float var = red[0] * (1.0f / (DMODEL - 1));
    float rstd = rsqrtf(var + LN_EPS);

    float4 msv = ((const float4*)mean_scale)[t];
    float4 ssv = ((const float4*)std_scale)[t];
    float4 o;
    o.x = dx * rstd * ssv.x + msv.x;
    o.y = dy * rstd * ssv.y + msv.y;
    o.z = dz * rstd * ssv.z + msv.z;
    o.w = dw * rstd * ssv.w + msv.w;
    ((float4*)(out + (size_t)row*DMODEL))[t] = o;
}

// ---------------- SGEMM: C[m,n] = sum_k A[m,k] * W[n,k]  (+ epilogue) ----------------
// A: [M,K] row-major, W: [N,K] row-major. M,N % 128 == 0, K % 16 == 0.
#define EPI_NONE 0
#define EPI_GELU 1
#define EPI_ADD  2

__device__ __forceinline__ float gelu_exact(float v) {
    return 0.5f * v * (1.0f + erff(v * 0.7071067811865476f));
}

template<int EPI>
__global__ __launch_bounds__(256, 2) void gemm_tn(
    const float* __restrict__ A, const float* __restrict__ W,
    const float* __restrict__ R, float* __restrict__ C,
    int M, int N, int K)
{
    __shared__ __align__(16) float As[16][132];
    __shared__ __align__(16) float Bs[16][132];

    int t  = threadIdx.x;
    int tx = t & 15, ty = t >> 4;
    const float* Ab = A + (size_t)(blockIdx.y * 128) * K;
    const float* Wb = W + (size_t)(blockIdx.x * 128) * K;

    float acc[8][8];
    #pragma unroll
    for (int i = 0; i < 8; i++)
        #pragma unroll
        for (int j = 0; j < 8; j++) acc[i][j] = 0.0f;

    int lrow = t >> 2;            // 0..63
    int lkc  = (t & 3) * 4;       // 0,4,8,12

    for (int k0 = 0; k0 < K; k0 += 16) {
        #pragma unroll
        for (int i = 0; i < 2; i++) {
            int row = lrow + i * 64;
            float4 av = *(const float4*)(Ab + (size_t)row * K + k0 + lkc);
            As[lkc+0][row] = av.x; As[lkc+1][row] = av.y;
            As[lkc+2][row] = av.z; As[lkc+3][row] = av.w;
            float4 wv = *(const float4*)(Wb + (size_t)row * K + k0 + lkc);
            Bs[lkc+0][row] = wv.x; Bs[lkc+1][row] = wv.y;
            Bs[lkc+2][row] = wv.z; Bs[lkc+3][row] = wv.w;
        }
        __syncthreads();
        #pragma unroll
        for (int kk = 0; kk < 16; kk++) {
            float a[8], b[8];
            *(float4*)&a[0] = *(const float4*)&As[kk][ty*8];
            *(float4*)&a[4] = *(const float4*)&As[kk][ty*8 + 4];
            *(float4*)&b[0] = *(const float4*)&Bs[kk][tx*8];
            *(float4*)&b[4] = *(const float4*)&Bs[kk][tx*8 + 4];
            #pragma unroll
            for (int i = 0; i < 8; i++)
                #pragma unroll
                for (int j = 0; j < 8; j++)
                    acc[i][j] = fmaf(a[i], b[j], acc[i][j]);
        }
        __syncthreads();
    }

    int crow0 = blockIdx.y * 128 + ty * 8;
    int ccol0 = blockIdx.x * 128 + tx * 8;
    #pragma unroll
    for (int i = 0; i < 8; i++) {
        size_t base = (size_t)(crow0 + i) * N + ccol0;
        #pragma unroll
        for (int j = 0; j < 8; j += 4) {
            float4 v = make_float4(acc[i][j], acc[i][j+1], acc[i][j+2], acc[i][j+3]);
            if (EPI == EPI_GELU) {
                v.x = gelu_exact(v.x); v.y = gelu_exact(v.y);
                v.z = gelu_exact(v.z); v.w = gelu_exact(v.w);
            } else if (EPI == EPI_ADD) {
                float4 r = *(const float4*)(R + base + j);
                v.x += r.x; v.y += r.y; v.z += r.z; v.w += r.w;
            }
            *(float4*)(C + base + j) = v;
        }
    }
}

// ---------------- Flash attention, fp32, causal ----------------
// Q/K/V/O: [B, S, D] fp32, head h = columns [h*64, h*64+64). Q pre-scaled by 1/8.
// Block: (qt, h, b). 256 threads, 4x4 micro-tile over a 64x64 score tile.
__global__ __launch_bounds__(256) void attn_kernel(
    const float* __restrict__ Q, const float* __restrict__ K,
    const float* __restrict__ V, float* __restrict__ O)
{
    extern __shared__ __align__(16) float sm[];
    const int SD = 68;
    float* Qs = sm;
    float* Ks = sm + 64*SD;
    float* Vs = sm + 2*64*SD;
    float* Ps = sm + 3*64*SD;

    int qt = blockIdx.x, h = blockIdx.y, b = blockIdx.z;
    int t = threadIdx.x;
    int tx = t & 15, ty = t >> 4;

    const float* Qb = Q + ((size_t)b*SEQ + (size_t)qt*64) * DMODEL + h*HD;
    const float* Kb = K + ((size_t)b*SEQ) * DMODEL + h*HD;
    const float* Vb = V + ((size_t)b*SEQ) * DMODEL + h*HD;

    // load + scale Q tile
    for (int i = t; i < 64*16; i += 256) {
        int r = i >> 4, c = (i & 15) * 4;
        float4 v = *(const float4*)(Qb + (size_t)r * DMODEL + c);
        v.x *= 0.125f; v.y *= 0.125f; v.z *= 0.125f; v.w *= 0.125f;
        *(float4*)(Qs + r*SD + c) = v;
    }

    float acc[4][4];
    #pragma unroll
    for (int i = 0; i < 4; i++)
        #pragma unroll
        for (int j = 0; j < 4; j++) acc[i][j] = 0.0f;
    float mrow[4] = {-1e30f, -1e30f, -1e30f, -1e30f};
    float lrow[4] = {0.0f, 0.0f, 0.0f, 0.0f};

    for (int kt = 0; kt <= qt; kt++) {
        __syncthreads();   // prior PV done (and Qs visible on first iter)
        const float* Kt = Kb + (size_t)kt * 64 * DMODEL;
        const float* Vt = Vb + (size_t)kt * 64 * DMODEL;
        for (int i = t; i < 64*16; i += 256) {
            int r = i >> 4, c = (i & 15) * 4;
            *(float4*)(Ks + r*SD + c) = *(const float4*)(Kt + (size_t)r * DMODEL + c);
            *(float4*)(Vs + r*SD + c) = *(const float4*)(Vt + (size_t)r * DMODEL + c);
        }
        __syncthreads();

        // scores: s[i][j] = sum_d Qs[ty*4+i][d] * Ks[tx*4+j][d]
        float s[4][4];
        #pragma unroll
        for (int i = 0; i < 4; i++)
            #pragma unroll
            for (int j = 0; j < 4; j++) s[i][j] = 0.0f;
        #pragma unroll
        for (int d0 = 0; d0 < 64; d0 += 4) {
            float4 qv[4], kv[4];
            #pragma unroll
            for (int i = 0; i < 4; i++) qv[i] = *(const float4*)(Qs + (ty*4+i)*SD + d0);
            #pragma unroll
            for (int j = 0; j < 4; j++) kv[j] = *(const float4*)(Ks + (tx*4+j)*SD + d0);
            #pragma unroll
            for (int i = 0; i < 4; i++)
                #pragma unroll
                for (int j = 0; j < 4; j++)
                    s[i][j] += qv[i].x*kv[j].x + qv[i].y*kv[j].y
                             + qv[i].z*kv[j].z + qv[i].w*kv[j].w;
        }
        if (kt == qt) {
            #pragma unroll
            for (int i = 0; i < 4; i++)
                #pragma unroll
                for (int j = 0; j < 4; j++)
                    if (tx*4 + j > ty*4 + i) s[i][j] = -1e30f;
        }

        // online softmax; row reduction across the 16-lane tx group
        #pragma unroll
        for (int i = 0; i < 4; i++) {
            float rm = fmaxf(fmaxf(s[i][0], s[i][1]), fmaxf(s[i][2], s[i][3]));
            #pragma unroll
            for (int m = 8; m > 0; m >>= 1)
                rm = fmaxf(rm, __shfl_xor_sync(0xffffffffu, rm, m));
            float mn = fmaxf(mrow[i], rm);
            float corr = __expf(mrow[i] - mn);
            float p0 = __expf(s[i][0] - mn);
            float p1 = __expf(s[i][1] - mn);
            float p2 = __expf(s[i][2] - mn);
            float p3 = __expf(s[i][3] - mn);
            float rs = p0 + p1 + p2 + p3;
            #pragma unroll
            for (int m = 8; m > 0; m >>= 1)
                rs += __shfl_xor_sync(0xffffffffu, rs, m);
            lrow[i] = lrow[i] * corr + rs;
            mrow[i] = mn;
            #pragma unroll
            for (int j = 0; j < 4; j++) acc[i][j] *= corr;
            *(float4*)(Ps + (ty*4+i)*SD + tx*4) = make_float4(p0, p1, p2, p3);
        }
        __syncthreads();

        // PV: acc[i][j] += sum_k Ps[row_i][k] * Vs[k][col_j]
        #pragma unroll
        for (int k0 = 0; k0 < 64; k0 += 4) {
            float4 p4[4];
            #pragma unroll
            for (int i = 0; i < 4; i++) p4[i] = *(const float4*)(Ps + (ty*4+i)*SD + k0);
            float4 v0 = *(const float4*)(Vs + (k0+0)*SD + tx*4);
            float4 v1 = *(const float4*)(Vs + (k0+1)*SD + tx*4);
            float4 v2 = *(const float4*)(Vs + (k0+2)*SD + tx*4);
            float4 v3 = *(const float4*)(Vs + (k0+3)*SD + tx*4);
            #pragma unroll
            for (int i = 0; i < 4; i++) {
                acc[i][0] += p4[i].x*v0.x + p4[i].y*v1.x + p4[i].z*v2.x + p4[i].w*v3.x;
                acc[i][1] += p4[i].x*v0.y + p4[i].y*v1.y + p4[i].z*v2.y + p4[i].w*v3.y;
                acc[i][2] += p4[i].x*v0.z + p4[i].y*v1.z + p4[i].z*v2.z + p4[i].w*v3.z;
                acc[i][3] += p4[i].x*v0.w + p4[i].y*v1.w + p4[i].z*v2.w + p4[i].w*v3.w;
            }
        }
    }

    float* Ob = O + ((size_t)b*SEQ + (size_t)qt*64) * DMODEL + h*HD;
    #pragma unroll
    for (int i = 0; i < 4; i++) {
        float inv = 1.0f / lrow[i];
        float4 o = make_float4(acc[i][0]*inv, acc[i][1]*inv, acc[i][2]*inv, acc[i][3]*inv);
        *(float4*)(Ob + (size_t)(ty*4+i) * DMODEL + tx*4) = o;
    }
}

// ---------------- launch ----------------
extern "C" void kernel_launch(void* const* d_in, const int* in_sizes, int n_in,
                              void* d_out, int out_size)
{
    const float* x    = (const float*)d_in[0];
    const float* Wq   = (const float*)d_in[1];
    const float* Wk   = (const float*)d_in[2];
    const float* Wv   = (const float*)d_in[3];
    const float* Wo   = (const float*)d_in[4];
    const float* Wup  = (const float*)d_in[5];
    const float* Wdn  = (const float*)d_in[6];
    const float* ln1m = (const float*)d_in[7];
    const float* ln1s = (const float*)d_in[8];
    const float* ln2m = (const float*)d_in[9];
    const float* ln2s = (const float*)d_in[10];
    float* out = (float*)d_out;

    float *b0, *b1, *b2, *b3, *b4, *bm;
    cudaGetSymbolAddress((void**)&b0, g_buf0);
    cudaGetSymbolAddress((void**)&b1, g_buf1);
    cudaGetSymbolAddress((void**)&b2, g_buf2);
    cudaGetSymbolAddress((void**)&b3, g_buf3);
    cudaGetSymbolAddress((void**)&b4, g_buf4);
    cudaGetSymbolAddress((void**)&bm, g_mid);

    const int attn_smem = 4 * 64 * 68 * (int)sizeof(float);  // 69632 B
    cudaFuncSetAttribute(attn_kernel, cudaFuncAttributeMaxDynamicSharedMemorySize, attn_smem);

    dim3 gproj(DMODEL/128, MROWS/128);   // (8, 32)
    dim3 gup  (DFF/128,    MROWS/128);   // (32, 32)

    // LN1
    ln_kernel<<<MROWS, 256>>>(x, ln1m, ln1s, b0);
    // QKV
    gemm_tn<EPI_NONE><<<gproj, 256>>>(b0, Wq, nullptr, b1, MROWS, DMODEL, DMODEL);
    gemm_tn<EPI_NONE><<<gproj, 256>>>(b0, Wk, nullptr, b2, MROWS, DMODEL, DMODEL);
    gemm_tn<EPI_NONE><<<gproj, 256>>>(b0, Wv, nullptr, b3, MROWS, DMODEL, DMODEL);
    // attention (O overwrites b0)
    attn_kernel<<<dim3(SEQ/64, NH, BDIM), 256, attn_smem>>>(b1, b2, b3, b0);
    // out proj + residual -> y1
    gemm_tn<EPI_ADD><<<gproj, 256>>>(b0, Wo, x, b4, MROWS, DMODEL, DMODEL);
    // LN2 (into b1)
    ln_kernel<<<MROWS, 256>>>(b4, ln2m, ln2s, b1);
    // MLP up + GELU
    gemm_tn<EPI_GELU><<<gup, 256>>>(b1, Wup, nullptr, bm, MROWS, DFF, DMODEL);
    // MLP down + residual -> out
    gemm_tn<EPI_ADD><<<gproj, 256>>>(bm, Wdn, b4, out, MROWS, DMODEL, DFF);
}

// round 3
// speedup vs baseline: 2.0406x; 2.0406x over previous
#include <cuda_runtime.h>
#include <math.h>
#include <stdint.h>

#define BDIM 2
#define SEQ  2048
#define DMODEL 1024
#define NH   16
#define HD   64
#define MROWS (BDIM*SEQ)     // 4096
#define DFF  4096
#define LN_EPS 1e-9f

// ---------------- scratch (device globals; no allocation allowed) ----------------
__device__ float g_buf0[(size_t)MROWS*DMODEL];  // ln1 out, then attention O
__device__ float g_buf1[(size_t)MROWS*DMODEL];  // Q, then ln2 out
__device__ float g_buf2[(size_t)MROWS*DMODEL];  // K
__device__ float g_buf3[(size_t)MROWS*DMODEL];  // V
__device__ float g_buf4[(size_t)MROWS*DMODEL];  // y1 = x + attn
__device__ float g_mid [(size_t)MROWS*DFF];     // MLP mid (gelu)

// ---------------- LayerNorm (torch var: ddof=1), two-pass ----------------
__global__ __launch_bounds__(256) void ln_kernel(
    const float* __restrict__ x, const float* __restrict__ mean_scale,
    const float* __restrict__ std_scale, float* __restrict__ out)
{
    int row = blockIdx.x;
    int t = threadIdx.x;
    const float4* xr = (const float4*)(x + (size_t)row*DMODEL);
    float4 v = xr[t];

    __shared__ float red[8];
    float s = v.x + v.y + v.z + v.w;
    #pragma unroll
    for (int m = 16; m > 0; m >>= 1) s += __shfl_xor_sync(0xffffffffu, s, m);
    if ((t & 31) == 0) red[t >> 5] = s;
    __syncthreads();
    if (t < 8) {
        float r = red[t];
        #pragma unroll
        for (int m = 4; m > 0; m >>= 1) r += __shfl_xor_sync(0xffu, r, m);
        if (t == 0) red[0] = r;
    }
    __syncthreads();
    float mean = red[0] * (1.0f / DMODEL);
    float dx = v.x - mean, dy = v.y - mean, dz = v.z - mean, dw = v.w - mean;
    float q = dx*dx + dy*dy + dz*dz + dw*dw;
    __syncthreads();
    #pragma unroll
    for (int m = 16; m > 0; m >>= 1) q += __shfl_xor_sync(0xffffffffu, q, m);
    if ((t & 31) == 0) red[t >> 5] = q;
    __syncthreads();
    if (t < 8) {
        float r = red[t];
        #pragma unroll
        for (int m = 4; m > 0; m >>= 1) r += __shfl_xor_sync(0xffu, r, m);
        if (t == 0) red[0] = r;
    }
    __syncthreads();
    float var = red[0] * (1.0f / (DMODEL - 1));
    float rstd = rsqrtf(var + LN_EPS);

    float4 msv = ((const float4*)mean_scale)[t];
    float4 ssv = ((const float4*)std_scale)[t];
    float4 o;
    o.x = dx * rstd * ssv.x + msv.x;
    o.y = dy * rstd * ssv.y + msv.y;
    o.z = dz * rstd * ssv.z + msv.z;
    o.w = dw * rstd * ssv.w + msv.w;
    ((float4*)(out + (size_t)row*DMODEL))[t] = o;
}

// ---------------- TF32 tensor-core GEMM ----------------
// C[m,n] = sum_k A[m,k] * W[n,k] (+ epilogue). M,N % 128 == 0, K % 32 == 0.
#define EPI_NONE 0
#define EPI_GELU 1
#define EPI_ADD  2

#define TBM 128
#define TBK 32
#define TSTR 36   // smem row stride (floats): bank = (4*row + k) % 32 -> conflict-free frags
#define TILE_FLOATS (TBM*TSTR)   // 4608 floats per (matrix, stage)

__device__ __forceinline__ float gelu_exact(float v) {
    return 0.5f * v * (1.0f + erff(v * 0.7071067811865476f));
}

__device__ __forceinline__ void cp16(void* s, const void* g) {
    uint32_t sa = (uint32_t)__cvta_generic_to_shared(s);
    asm volatile("cp.async.cg.shared.global [%0], [%1], 16;" :: "r"(sa), "l"(g));
}
__device__ __forceinline__ void cp_commit() {
    asm volatile("cp.async.commit_group;");
}
template<int NGRP> __device__ __forceinline__ void cp_wait() {
    asm volatile("cp.async.wait_group %0;" :: "n"(NGRP));
}

__device__ __forceinline__ void mma_tf32(
    float& c0, float& c1, float& c2, float& c3,
    uint32_t a0, uint32_t a1, uint32_t a2, uint32_t a3,
    uint32_t b0, uint32_t b1)
{
    asm volatile(
        "mma.sync.aligned.m16n8k8.row.col.f32.tf32.tf32.f32 "
        "{%0,%1,%2,%3}, {%4,%5,%6,%7}, {%8,%9}, {%0,%1,%2,%3};"
        : "+f"(c0), "+f"(c1), "+f"(c2), "+f"(c3)
        : "r"(a0), "r"(a1), "r"(a2), "r"(a3), "r"(b0), "r"(b1));
}

template<int EPI>
__global__ __launch_bounds__(256, 2) void gemm_tc(
    const float* __restrict__ A, const float* __restrict__ W,
    const float* __restrict__ R, float* __restrict__ C,
    int M, int N, int K)
{
    extern __shared__ __align__(16) float smem[];
    float* As = smem;                    // [2][128][36]
    float* Bs = smem + 2*TILE_FLOATS;    // [2][128][36]

    int t = threadIdx.x;
    int warp = t >> 5, lane = t & 31;
    int wm = warp & 1, wn = warp >> 1;       // warps: 2 (m) x 4 (n)
    int g = lane >> 2, q = lane & 3;

    const float* Ab = A + (size_t)(blockIdx.y * TBM) * K;
    const float* Wb = W + (size_t)(blockIdx.x * TBM) * K;

    float acc[4][4][4];
    #pragma unroll
    for (int i = 0; i < 4; i++)
        #pragma unroll
        for (int j = 0; j < 4; j++)
            #pragma unroll
            for (int c = 0; c < 4; c++) acc[i][j][c] = 0.0f;

    int nk = K / TBK;

    {   // prologue: tile 0 -> stage 0
        #pragma unroll
        for (int i = 0; i < 4; i++) {
            int lin = t + i * 256;
            int row = lin >> 3, cc = (lin & 7) << 2;
            cp16(&As[row*TSTR + cc], Ab + (size_t)row * K + cc);
            cp16(&Bs[row*TSTR + cc], Wb + (size_t)row * K + cc);
        }
        cp_commit();
    }

    for (int kt = 0; kt < nk; kt++) {
        int buf = kt & 1;
        if (kt + 1 < nk) {
            int nbuf = (kt + 1) & 1;
            int k0 = (kt + 1) * TBK;
            #pragma unroll
            for (int i = 0; i < 4; i++) {
                int lin = t + i * 256;
                int row = lin >> 3, cc = (lin & 7) << 2;
                cp16(&As[nbuf*TILE_FLOATS + row*TSTR + cc], Ab + (size_t)row * K + k0 + cc);
                cp16(&Bs[nbuf*TILE_FLOATS + row*TSTR + cc], Wb + (size_t)row * K + k0 + cc);
            }
            cp_commit();
            cp_wait<1>();
        } else {
            cp_wait<0>();
        }
        __syncthreads();

        const float* Abs = As + buf * TILE_FLOATS;
        const float* Bbs = Bs + buf * TILE_FLOATS;
        #pragma unroll
        for (int ks = 0; ks < 4; ks++) {
            int kb = ks * 8;
            uint32_t af[4][4], bf[4][2];
            #pragma unroll
            for (int mt = 0; mt < 4; mt++) {
                int m = wm*64 + mt*16 + g;
                af[mt][0] = __float_as_uint(Abs[(size_t)m*TSTR + kb + q]);
                af[mt][1] = __float_as_uint(Abs[(size_t)(m+8)*TSTR + kb + q]);
                af[mt][2] = __float_as_uint(Abs[(size_t)m*TSTR + kb + q + 4]);
                af[mt][3] = __float_as_uint(Abs[(size_t)(m+8)*TSTR + kb + q + 4]);
            }
            #pragma unroll
            for (int nt = 0; nt < 4; nt++) {
                int n = wn*32 + nt*8 + g;
                bf[nt][0] = __float_as_uint(Bbs[(size_t)n*TSTR + kb + q]);
                bf[nt][1] = __float_as_uint(Bbs[(size_t)n*TSTR + kb + q + 4]);
            }
            #pragma unroll
            for (int mt = 0; mt < 4; mt++)
                #pragma unroll
                for (int nt = 0; nt < 4; nt++)
                    mma_tf32(acc[mt][nt][0], acc[mt][nt][1], acc[mt][nt][2], acc[mt][nt][3],
                             af[mt][0], af[mt][1], af[mt][2], af[mt][3],
                             bf[nt][0], bf[nt][1]);
        }
        __syncthreads();
    }

    // epilogue
    int browb = blockIdx.y * TBM + wm * 64;
    int bcolb = blockIdx.x * TBM + wn * 32;
    #pragma unroll
    for (int mt = 0; mt < 4; mt++) {
        #pragma unroll
        for (int nt = 0; nt < 4; nt++) {
            int r0 = browb + mt*16 + g;
            int c0 = bcolb + nt*8 + 2*q;
            #pragma unroll
            for (int half = 0; half < 2; half++) {
                int r = r0 + half*8;
                float vx = acc[mt][nt][half*2 + 0];
                float vy = acc[mt][nt][half*2 + 1];
                size_t base = (size_t)r * N + c0;
                if (EPI == EPI_GELU) {
                    vx = gelu_exact(vx); vy = gelu_exact(vy);
                } else if (EPI == EPI_ADD) {
                    float2 rr = *(const float2*)(R + base);
                    vx += rr.x; vy += rr.y;
                }
                float2 o; o.x = vx; o.y = vy;
                *(float2*)(C + base) = o;
            }
        }
    }
}

// ---------------- Flash attention, fp32, causal ----------------
__global__ __launch_bounds__(256) void attn_kernel(
    const float* __restrict__ Q, const float* __restrict__ K,
    const float* __restrict__ V, float* __restrict__ O)
{
    extern __shared__ __align__(16) float sm[];
    const int SD = 68;
    float* Qs = sm;
    float* Ks = sm + 64*SD;
    float* Vs = sm + 2*64*SD;
    float* Ps = sm + 3*64*SD;

    int qt = blockIdx.x, h = blockIdx.y, b = blockIdx.z;
    int t = threadIdx.x;
    int tx = t & 15, ty = t >> 4;

    const float* Qb = Q + ((size_t)b*SEQ + (size_t)qt*64) * DMODEL + h*HD;
    const float* Kb = K + ((size_t)b*SEQ) * DMODEL + h*HD;
    const float* Vb = V + ((size_t)b*SEQ) * DMODEL + h*HD;

    for (int i = t; i < 64*16; i += 256) {
        int r = i >> 4, c = (i & 15) * 4;
        float4 v = *(const float4*)(Qb + (size_t)r * DMODEL + c);
        v.x *= 0.125f; v.y *= 0.125f; v.z *= 0.125f; v.w *= 0.125f;
        *(float4*)(Qs + r*SD + c) = v;
    }

    float acc[4][4];
    #pragma unroll
    for (int i = 0; i < 4; i++)
        #pragma unroll
        for (int j = 0; j < 4; j++) acc[i][j] = 0.0f;
    float mrow[4] = {-1e30f, -1e30f, -1e30f, -1e30f};
    float lrow[4] = {0.0f, 0.0f, 0.0f, 0.0f};

    for (int kt = 0; kt <= qt; kt++) {
        __syncthreads();
        const float* Kt = Kb + (size_t)kt * 64 * DMODEL;
        const float* Vt = Vb + (size_t)kt * 64 * DMODEL;
        for (int i = t; i < 64*16; i += 256) {
            int r = i >> 4, c = (i & 15) * 4;
            *(float4*)(Ks + r*SD + c) = *(const float4*)(Kt + (size_t)r * DMODEL + c);
            *(float4*)(Vs + r*SD + c) = *(const float4*)(Vt + (size_t)r * DMODEL + c);
        }
        __syncthreads();

        float s[4][4];
        #pragma unroll
        for (int i = 0; i < 4; i++)
            #pragma unroll
            for (int j = 0; j < 4; j++) s[i][j] = 0.0f;
        #pragma unroll
        for (int d0 = 0; d0 < 64; d0 += 4) {
            float4 qv[4], kv[4];
            #pragma unroll
            for (int i = 0; i < 4; i++) qv[i] = *(const float4*)(Qs + (ty*4+i)*SD + d0);
            #pragma unroll
            for (int j = 0; j < 4; j++) kv[j] = *(const float4*)(Ks + (tx*4+j)*SD + d0);
            #pragma unroll
            for (int i = 0; i < 4; i++)
                #pragma unroll
                for (int j = 0; j < 4; j++)
                    s[i][j] += qv[i].x*kv[j].x + qv[i].y*kv[j].y
                             + qv[i].z*kv[j].z + qv[i].w*kv[j].w;
        }
        if (kt == qt) {
            #pragma unroll
            for (int i = 0; i < 4; i++)
                #pragma unroll
                for (int j = 0; j < 4; j++)
                    if (tx*4 + j > ty*4 + i) s[i][j] = -1e30f;
        }

        #pragma unroll
        for (int i = 0; i < 4; i++) {
            float rm = fmaxf(fmaxf(s[i][0], s[i][1]), fmaxf(s[i][2], s[i][3]));
            #pragma unroll
            for (int m = 8; m > 0; m >>= 1)
                rm = fmaxf(rm, __shfl_xor_sync(0xffffffffu, rm, m));
            float mn = fmaxf(mrow[i], rm);
            float corr = __expf(mrow[i] - mn);
            float p0 = __expf(s[i][0] - mn);
            float p1 = __expf(s[i][1] - mn);
            float p2 = __expf(s[i][2] - mn);
            float p3 = __expf(s[i][3] - mn);
            float rs = p0 + p1 + p2 + p3;
            #pragma unroll
            for (int m = 8; m > 0; m >>= 1)
                rs += __shfl_xor_sync(0xffffffffu, rs, m);
            lrow[i] = lrow[i] * corr + rs;
            mrow[i] = mn;
            #pragma unroll
            for (int j = 0; j < 4; j++) acc[i][j] *= corr;
            *(float4*)(Ps + (ty*4+i)*SD + tx*4) = make_float4(p0, p1, p2, p3);
        }
        __syncthreads();

        #pragma unroll
        for (int k0 = 0; k0 < 64; k0 += 4) {
            float4 p4[4];
            #pragma unroll
            for (int i = 0; i < 4; i++) p4[i] = *(const float4*)(Ps + (ty*4+i)*SD + k0);
            float4 v0 = *(const float4*)(Vs + (k0+0)*SD + tx*4);
            float4 v1 = *(const float4*)(Vs + (k0+1)*SD + tx*4);
            float4 v2 = *(const float4*)(Vs + (k0+2)*SD + tx*4);
            float4 v3 = *(const float4*)(Vs + (k0+3)*SD + tx*4);
            #pragma unroll
            for (int i = 0; i < 4; i++) {
                acc[i][0] += p4[i].x*v0.x + p4[i].y*v1.x + p4[i].z*v2.x + p4[i].w*v3.x;
                acc[i][1] += p4[i].x*v0.y + p4[i].y*v1.y + p4[i].z*v2.y + p4[i].w*v3.y;
                acc[i][2] += p4[i].x*v0.z + p4[i].y*v1.z + p4[i].z*v2.z + p4[i].w*v3.z;
                acc[i][3] += p4[i].x*v0.w + p4[i].y*v1.w + p4[i].z*v2.w + p4[i].w*v3.w;
            }
        }
    }

    float* Ob = O + ((size_t)b*SEQ + (size_t)qt*64) * DMODEL + h*HD;
    #pragma unroll
    for (int i = 0; i < 4; i++) {
        float inv = 1.0f / lrow[i];
        float4 o = make_float4(acc[i][0]*inv, acc[i][1]*inv, acc[i][2]*inv, acc[i][3]*inv);
        *(float4*)(Ob + (size_t)(ty*4+i) * DMODEL + tx*4) = o;
    }
}

// ---------------- launch ----------------
extern "C" void kernel_launch(void* const* d_in, const int* in_sizes, int n_in,
                              void* d_out, int out_size)
{
    const float* x    = (const float*)d_in[0];
    const float* Wq   = (const float*)d_in[1];
    const float* Wk   = (const float*)d_in[2];
    const float* Wv   = (const float*)d_in[3];
    const float* Wo   = (const float*)d_in[4];
    const float* Wup  = (const float*)d_in[5];
    const float* Wdn  = (const float*)d_in[6];
    const float* ln1m = (const float*)d_in[7];
    const float* ln1s = (const float*)d_in[8];
    const float* ln2m = (const float*)d_in[9];
    const float* ln2s = (const float*)d_in[10];
    float* out = (float*)d_out;

    float *b0, *b1, *b2, *b3, *b4, *bm;
    cudaGetSymbolAddress((void**)&b0, g_buf0);
    cudaGetSymbolAddress((void**)&b1, g_buf1);
    cudaGetSymbolAddress((void**)&b2, g_buf2);
    cudaGetSymbolAddress((void**)&b3, g_buf3);
    cudaGetSymbolAddress((void**)&b4, g_buf4);
    cudaGetSymbolAddress((void**)&bm, g_mid);

    const int gemm_smem = 4 * TILE_FLOATS * (int)sizeof(float);  // 73728 B
    cudaFuncSetAttribute(gemm_tc<EPI_NONE>, cudaFuncAttributeMaxDynamicSharedMemorySize, gemm_smem);
    cudaFuncSetAttribute(gemm_tc<EPI_GELU>, cudaFuncAttributeMaxDynamicSharedMemorySize, gemm_smem);
    cudaFuncSetAttribute(gemm_tc<EPI_ADD>,  cudaFuncAttributeMaxDynamicSharedMemorySize, gemm_smem);

    const int attn_smem = 4 * 64 * 68 * (int)sizeof(float);  // 69632 B
    cudaFuncSetAttribute(attn_kernel, cudaFuncAttributeMaxDynamicSharedMemorySize, attn_smem);

    dim3 gproj(DMODEL/128, MROWS/128);   // (8, 32)
    dim3 gup  (DFF/128,    MROWS/128);   // (32, 32)

    // LN1
    ln_kernel<<<MROWS, 256>>>(x, ln1m, ln1s, b0);
    // QKV
    gemm_tc<EPI_NONE><<<gproj, 256, gemm_smem>>>(b0, Wq, nullptr, b1, MROWS, DMODEL, DMODEL);
    gemm_tc<EPI_NONE><<<gproj, 256, gemm_smem>>>(b0, Wk, nullptr, b2, MROWS, DMODEL, DMODEL);
    gemm_tc<EPI_NONE><<<gproj, 256, gemm_smem>>>(b0, Wv, nullptr, b3, MROWS, DMODEL, DMODEL);
    // attention (O overwrites b0)
    attn_kernel<<<dim3(SEQ/64, NH, BDIM), 256, attn_smem>>>(b1, b2, b3, b0);
    // out proj + residual -> y1
    gemm_tc<EPI_ADD><<<gproj, 256, gemm_smem>>>(b0, Wo, x, b4, MROWS, DMODEL, DMODEL);
    // LN2 (into b1)
    ln_kernel<<<MROWS, 256>>>(b4, ln2m, ln2s, b1);
    // MLP up + GELU
    gemm_tc<EPI_GELU><<<gup, 256, gemm_smem>>>(b1, Wup, nullptr, bm, MROWS, DFF, DMODEL);
    // MLP down + residual -> out
    gemm_tc<EPI_ADD><<<gproj, 256, gemm_smem>>>(bm, Wdn, b4, out, MROWS, DMODEL, DFF);
}

// round 4
// speedup vs baseline: 3.3953x; 1.6639x over previous
#include <cuda_runtime.h>
#include <math.h>
#include <stdint.h>

#define BDIM 2
#define SEQ  2048
#define DMODEL 1024
#define NH   16
#define HD   64
#define MROWS (BDIM*SEQ)     // 4096
#define DFF  4096
#define LN_EPS 1e-9f

// ---------------- scratch ----------------
__device__ float g_buf0[(size_t)MROWS*DMODEL];  // ln1 out, then attention O
__device__ float g_buf1[(size_t)MROWS*DMODEL];  // Q, then ln2 out
__device__ float g_buf2[(size_t)MROWS*DMODEL];  // K
__device__ float g_buf3[(size_t)MROWS*DMODEL];  // V
__device__ float g_buf4[(size_t)MROWS*DMODEL];  // y1 = x + attn
__device__ float g_mid [(size_t)MROWS*DFF];     // MLP mid (gelu)

// round-to-nearest tf32 (kills truncation bias of raw-bit mma operands)
__device__ __forceinline__ uint32_t f2tf32(float x) {
    uint32_t u; asm("cvt.rna.tf32.f32 %0, %1;" : "=r"(u) : "f"(x));
    return u;
}
__device__ __forceinline__ float rtf(float x) { return __uint_as_float(f2tf32(x)); }

// ---------------- LayerNorm (ddof=1) ----------------
__global__ __launch_bounds__(256) void ln_kernel(
    const float* __restrict__ x, const float* __restrict__ mean_scale,
    const float* __restrict__ std_scale, float* __restrict__ out)
{
    int row = blockIdx.x;
    int t = threadIdx.x;
    const float4* xr = (const float4*)(x + (size_t)row*DMODEL);
    float4 v = xr[t];

    __shared__ float red[8];
    float s = v.x + v.y + v.z + v.w;
    #pragma unroll
    for (int m = 16; m > 0; m >>= 1) s += __shfl_xor_sync(0xffffffffu, s, m);
    if ((t & 31) == 0) red[t >> 5] = s;
    __syncthreads();
    if (t < 8) {
        float r = red[t];
        #pragma unroll
        for (int m = 4; m > 0; m >>= 1) r += __shfl_xor_sync(0xffu, r, m);
        if (t == 0) red[0] = r;
    }
    __syncthreads();
    float mean = red[0] * (1.0f / DMODEL);
    float dx = v.x - mean, dy = v.y - mean, dz = v.z - mean, dw = v.w - mean;
    float q = dx*dx + dy*dy + dz*dz + dw*dw;
    __syncthreads();
    #pragma unroll
    for (int m = 16; m > 0; m >>= 1) q += __shfl_xor_sync(0xffffffffu, q, m);
    if ((t & 31) == 0) red[t >> 5] = q;
    __syncthreads();
    if (t < 8) {
        float r = red[t];
        #pragma unroll
        for (int m = 4; m > 0; m >>= 1) r += __shfl_xor_sync(0xffu, r, m);
        if (t == 0) red[0] = r;
    }
    __syncthreads();
    float var = red[0] * (1.0f / (DMODEL - 1));
    float rstd = rsqrtf(var + LN_EPS);

    float4 msv = ((const float4*)mean_scale)[t];
    float4 ssv = ((const float4*)std_scale)[t];
    float4 o;
    o.x = dx * rstd * ssv.x + msv.x;
    o.y = dy * rstd * ssv.y + msv.y;
    o.z = dz * rstd * ssv.z + msv.z;
    o.w = dw * rstd * ssv.w + msv.w;
    ((float4*)(out + (size_t)row*DMODEL))[t] = o;
}

// ---------------- TF32 tensor-core GEMM ----------------
#define EPI_NONE 0
#define EPI_GELU 1
#define EPI_ADD  2

#define TBM 128
#define TBK 32
#define TSTR 36
#define TILE_FLOATS (TBM*TSTR)

__device__ __forceinline__ float gelu_exact(float v) {
    return 0.5f * v * (1.0f + erff(v * 0.7071067811865476f));
}

__device__ __forceinline__ void cp16(void* s, const void* g) {
    uint32_t sa = (uint32_t)__cvta_generic_to_shared(s);
    asm volatile("cp.async.cg.shared.global [%0], [%1], 16;" :: "r"(sa), "l"(g));
}
__device__ __forceinline__ void cp_commit() {
    asm volatile("cp.async.commit_group;");
}
template<int NGRP> __device__ __forceinline__ void cp_wait() {
    asm volatile("cp.async.wait_group %0;" :: "n"(NGRP));
}

__device__ __forceinline__ void mma_tf32(
    float& c0, float& c1, float& c2, float& c3,
    uint32_t a0, uint32_t a1, uint32_t a2, uint32_t a3,
    uint32_t b0, uint32_t b1)
{
    asm volatile(
        "mma.sync.aligned.m16n8k8.row.col.f32.tf32.tf32.f32 "
        "{%0,%1,%2,%3}, {%4,%5,%6,%7}, {%8,%9}, {%0,%1,%2,%3};"
        : "+f"(c0), "+f"(c1), "+f"(c2), "+f"(c3)
        : "r"(a0), "r"(a1), "r"(a2), "r"(a3), "r"(b0), "r"(b1));
}

template<int EPI>
__device__ __forceinline__ void gemm_body(
    const float* __restrict__ A, const float* __restrict__ W,
    const float* __restrict__ R, float* __restrict__ C,
    int M, int N, int K)
{
    extern __shared__ __align__(16) float smem[];
    float* As = smem;                    // [2][128][36]
    float* Bs = smem + 2*TILE_FLOATS;

    int t = threadIdx.x;
    int warp = t >> 5, lane = t & 31;
    int wm = warp & 1, wn = warp >> 1;
    int g = lane >> 2, q = lane & 3;

    const float* Ab = A + (size_t)(blockIdx.y * TBM) * K;
    const float* Wb = W + (size_t)(blockIdx.x * TBM) * K;

    float acc[4][4][4];
    #pragma unroll
    for (int i = 0; i < 4; i++)
        #pragma unroll
        for (int j = 0; j < 4; j++)
            #pragma unroll
            for (int c = 0; c < 4; c++) acc[i][j][c] = 0.0f;

    int nk = K / TBK;

    {
        #pragma unroll
        for (int i = 0; i < 4; i++) {
            int lin = t + i * 256;
            int row = lin >> 3, cc = (lin & 7) << 2;
            cp16(&As[row*TSTR + cc], Ab + (size_t)row * K + cc);
            cp16(&Bs[row*TSTR + cc], Wb + (size_t)row * K + cc);
        }
        cp_commit();
    }

    for (int kt = 0; kt < nk; kt++) {
        int buf = kt & 1;
        if (kt + 1 < nk) {
            int nbuf = (kt + 1) & 1;
            int k0 = (kt + 1) * TBK;
            #pragma unroll
            for (int i = 0; i < 4; i++) {
                int lin = t + i * 256;
                int row = lin >> 3, cc = (lin & 7) << 2;
                cp16(&As[nbuf*TILE_FLOATS + row*TSTR + cc], Ab + (size_t)row * K + k0 + cc);
                cp16(&Bs[nbuf*TILE_FLOATS + row*TSTR + cc], Wb + (size_t)row * K + k0 + cc);
            }
            cp_commit();
            cp_wait<1>();
        } else {
            cp_wait<0>();
        }
        __syncthreads();

        const float* Abs = As + buf * TILE_FLOATS;
        const float* Bbs = Bs + buf * TILE_FLOATS;
        #pragma unroll
        for (int ks = 0; ks < 4; ks++) {
            int kb = ks * 8;
            uint32_t af[4][4], bf[4][2];
            #pragma unroll
            for (int mt = 0; mt < 4; mt++) {
                int m = wm*64 + mt*16 + g;
                af[mt][0] = f2tf32(Abs[(size_t)m*TSTR + kb + q]);
                af[mt][1] = f2tf32(Abs[(size_t)(m+8)*TSTR + kb + q]);
                af[mt][2] = f2tf32(Abs[(size_t)m*TSTR + kb + q + 4]);
                af[mt][3] = f2tf32(Abs[(size_t)(m+8)*TSTR + kb + q + 4]);
            }
            #pragma unroll
            for (int nt = 0; nt < 4; nt++) {
                int n = wn*32 + nt*8 + g;
                bf[nt][0] = f2tf32(Bbs[(size_t)n*TSTR + kb + q]);
                bf[nt][1] = f2tf32(Bbs[(size_t)n*TSTR + kb + q + 4]);
            }
            #pragma unroll
            for (int mt = 0; mt < 4; mt++)
                #pragma unroll
                for (int nt = 0; nt < 4; nt++)
                    mma_tf32(acc[mt][nt][0], acc[mt][nt][1], acc[mt][nt][2], acc[mt][nt][3],
                             af[mt][0], af[mt][1], af[mt][2], af[mt][3],
                             bf[nt][0], bf[nt][1]);
        }
        __syncthreads();
    }

    int browb = blockIdx.y * TBM + wm * 64;
    int bcolb = blockIdx.x * TBM + wn * 32;
    #pragma unroll
    for (int mt = 0; mt < 4; mt++) {
        #pragma unroll
        for (int nt = 0; nt < 4; nt++) {
            int r0 = browb + mt*16 + g;
            int c0 = bcolb + nt*8 + 2*q;
            #pragma unroll
            for (int half = 0; half < 2; half++) {
                int r = r0 + half*8;
                float vx = acc[mt][nt][half*2 + 0];
                float vy = acc[mt][nt][half*2 + 1];
                size_t base = (size_t)r * N + c0;
                if (EPI == EPI_GELU) {
                    vx = gelu_exact(vx); vy = gelu_exact(vy);
                } else if (EPI == EPI_ADD) {
                    float2 rr = *(const float2*)(R + base);
                    vx += rr.x; vy += rr.y;
                }
                float2 o; o.x = vx; o.y = vy;
                *(float2*)(C + base) = o;
            }
        }
    }
}

template<int EPI>
__global__ __launch_bounds__(256, 2) void gemm_tc(
    const float* __restrict__ A, const float* __restrict__ W,
    const float* __restrict__ R, float* __restrict__ C,
    int M, int N, int K)
{
    gemm_body<EPI>(A, W, R, C, M, N, K);
}

// fused QKV: grid.z picks the weight/output
__global__ __launch_bounds__(256, 2) void gemm_qkv(
    const float* __restrict__ A,
    const float* __restrict__ W0, const float* __restrict__ W1, const float* __restrict__ W2,
    float* __restrict__ C0, float* __restrict__ C1, float* __restrict__ C2)
{
    const float* W = (blockIdx.z == 0) ? W0 : (blockIdx.z == 1) ? W1 : W2;
    float* C = (blockIdx.z == 0) ? C0 : (blockIdx.z == 1) ? C1 : C2;
    gemm_body<EPI_NONE>(A, W, nullptr, C, MROWS, DMODEL, DMODEL);
}

// ---------------- Tensor-core flash attention (tf32), causal ----------------
// 128 threads = 4 warps; CTA handles 64 query rows; warp w -> rows 16w..16w+15.
#define ASD 68   // smem row stride (floats)

__global__ __launch_bounds__(128) void attn_tc(
    const float* __restrict__ Q, const float* __restrict__ K,
    const float* __restrict__ V, float* __restrict__ O)
{
    extern __shared__ __align__(16) float sm[];
    float* Qs = sm;                 // [64][68]
    float* Ks = sm + 64*ASD;        // [2][64][68]
    float* Vs = sm + 3*64*ASD;      // [2][64][68]
    float* Ps = sm + 5*64*ASD;      // [64][68]

    int qt = blockIdx.x, h = blockIdx.y, b = blockIdx.z;
    int t = threadIdx.x;
    int warp = t >> 5, lane = t & 31;
    int g = lane >> 2, q = lane & 3;

    const float* Qb = Q + ((size_t)b*SEQ + (size_t)qt*64) * DMODEL + h*HD;
    const float* Kb = K + (size_t)b*SEQ*DMODEL + h*HD;
    const float* Vb = V + (size_t)b*SEQ*DMODEL + h*HD;

    // Q tile: scale by 1/8, round to tf32 once
    for (int i = t; i < 64*16; i += 128) {
        int r = i >> 4, c = (i & 15) * 4;
        float4 v = *(const float4*)(Qb + (size_t)r * DMODEL + c);
        Qs[r*ASD + c + 0] = rtf(v.x * 0.125f);
        Qs[r*ASD + c + 1] = rtf(v.y * 0.125f);
        Qs[r*ASD + c + 2] = rtf(v.z * 0.125f);
        Qs[r*ASD + c + 3] = rtf(v.w * 0.125f);
    }

    // prologue: K/V tile 0 -> buf 0
    {
        const float* Kt = Kb;
        const float* Vt = Vb;
        for (int i = t; i < 64*16; i += 128) {
            int r = i >> 4, c = (i & 15) * 4;
            cp16(&Ks[r*ASD + c], Kt + (size_t)r * DMODEL + c);
            cp16(&Vs[r*ASD + c], Vt + (size_t)r * DMODEL + c);
        }
        cp_commit();
    }

    float acc[8][4];
    #pragma unroll
    for (int nt = 0; nt < 8; nt++)
        #pragma unroll
        for (int c = 0; c < 4; c++) acc[nt][c] = 0.0f;
    float m0 = -1e30f, m1 = -1e30f, l0 = 0.0f, l1 = 0.0f;

    int r0 = 16*warp + g;        // tile-relative rows this lane owns
    int r1 = r0 + 8;

    for (int kt = 0; kt <= qt; kt++) {
        int buf = kt & 1;
        if (kt < qt) {
            int nbuf = (kt + 1) & 1;
            const float* Kt = Kb + (size_t)(kt+1) * 64 * DMODEL;
            const float* Vt = Vb + (size_t)(kt+1) * 64 * DMODEL;
            float* Kd = Ks + nbuf*64*ASD;
            float* Vd = Vs + nbuf*64*ASD;
            for (int i = t; i < 64*16; i += 128) {
                int r = i >> 4, c = (i & 15) * 4;
                cp16(&Kd[r*ASD + c], Kt + (size_t)r * DMODEL + c);
                cp16(&Vd[r*ASD + c], Vt + (size_t)r * DMODEL + c);
            }
            cp_commit();
            cp_wait<1>();
        } else {
            cp_wait<0>();
        }
        __syncthreads();

        const float* Kbuf = Ks + buf*64*ASD;
        const float* Vbuf = Vs + buf*64*ASD;

        // ---- scores: S = Q Kt^T ----
        float sc[8][4];
        #pragma unroll
        for (int nt = 0; nt < 8; nt++)
            #pragma unroll
            for (int c = 0; c < 4; c++) sc[nt][c] = 0.0f;

        #pragma unroll
        for (int c8 = 0; c8 < 8; c8++) {
            int kb = c8 * 8;
            uint32_t a0 = __float_as_uint(Qs[(size_t)r0*ASD + kb + q]);
            uint32_t a1 = __float_as_uint(Qs[(size_t)r1*ASD + kb + q]);
            uint32_t a2 = __float_as_uint(Qs[(size_t)r0*ASD + kb + q + 4]);
            uint32_t a3 = __float_as_uint(Qs[(size_t)r1*ASD + kb + q + 4]);
            #pragma unroll
            for (int nt = 0; nt < 8; nt++) {
                uint32_t b0 = __float_as_uint(Kbuf[(size_t)(8*nt+g)*ASD + kb + q]);
                uint32_t b1 = __float_as_uint(Kbuf[(size_t)(8*nt+g)*ASD + kb + q + 4]);
                mma_tf32(sc[nt][0], sc[nt][1], sc[nt][2], sc[nt][3],
                         a0, a1, a2, a3, b0, b1);
            }
        }

        // causal mask on diagonal tile
        if (kt == qt) {
            #pragma unroll
            for (int nt = 0; nt < 8; nt++) {
                int col0 = 8*nt + 2*q;
                if (col0     > r0) sc[nt][0] = -1e30f;
                if (col0 + 1 > r0) sc[nt][1] = -1e30f;
                if (col0     > r1) sc[nt][2] = -1e30f;
                if (col0 + 1 > r1) sc[nt][3] = -1e30f;
            }
        }

        // ---- online softmax ----
        float tm0 = -1e30f, tm1 = -1e30f;
        #pragma unroll
        for (int nt = 0; nt < 8; nt++) {
            tm0 = fmaxf(tm0, fmaxf(sc[nt][0], sc[nt][1]));
            tm1 = fmaxf(tm1, fmaxf(sc[nt][2], sc[nt][3]));
        }
        tm0 = fmaxf(tm0, __shfl_xor_sync(0xffffffffu, tm0, 1));
        tm0 = fmaxf(tm0, __shfl_xor_sync(0xffffffffu, tm0, 2));
        tm1 = fmaxf(tm1, __shfl_xor_sync(0xffffffffu, tm1, 1));
        tm1 = fmaxf(tm1, __shfl_xor_sync(0xffffffffu, tm1, 2));

        float m0n = fmaxf(m0, tm0);
        float m1n = fmaxf(m1, tm1);
        float corr0 = __expf(m0 - m0n);
        float corr1 = __expf(m1 - m1n);

        float sum0 = 0.0f, sum1 = 0.0f;
        #pragma unroll
        for (int nt = 0; nt < 8; nt++) {
            float p0 = __expf(sc[nt][0] - m0n);
            float p1 = __expf(sc[nt][1] - m0n);
            float p2 = __expf(sc[nt][2] - m1n);
            float p3 = __expf(sc[nt][3] - m1n);
            sum0 += p0 + p1;
            sum1 += p2 + p3;
            float2 w0; w0.x = rtf(p0); w0.y = rtf(p1);
            float2 w1; w1.x = rtf(p2); w1.y = rtf(p3);
            *(float2*)&Ps[(size_t)r0*ASD + 8*nt + 2*q] = w0;
            *(float2*)&Ps[(size_t)r1*ASD + 8*nt + 2*q] = w1;
        }
        sum0 += __shfl_xor_sync(0xffffffffu, sum0, 1);
        sum0 += __shfl_xor_sync(0xffffffffu, sum0, 2);
        sum1 += __shfl_xor_sync(0xffffffffu, sum1, 1);
        sum1 += __shfl_xor_sync(0xffffffffu, sum1, 2);

        l0 = l0 * corr0 + sum0;
        l1 = l1 * corr1 + sum1;
        m0 = m0n; m1 = m1n;
        #pragma unroll
        for (int nt = 0; nt < 8; nt++) {
            acc[nt][0] *= corr0; acc[nt][1] *= corr0;
            acc[nt][2] *= corr1; acc[nt][3] *= corr1;
        }
        __syncwarp();   // P rows are warp-private; order stores before loads

        // ---- PV: acc += P @ V ----
        #pragma unroll
        for (int c8 = 0; c8 < 8; c8++) {
            int kb = c8 * 8;
            uint32_t a0 = __float_as_uint(Ps[(size_t)r0*ASD + kb + q]);
            uint32_t a1 = __float_as_uint(Ps[(size_t)r1*ASD + kb + q]);
            uint32_t a2 = __float_as_uint(Ps[(size_t)r0*ASD + kb + q + 4]);
            uint32_t a3 = __float_as_uint(Ps[(size_t)r1*ASD + kb + q + 4]);
            #pragma unroll
            for (int nt = 0; nt < 8; nt++) {
                uint32_t b0 = __float_as_uint(Vbuf[(size_t)(kb+q)*ASD + 8*nt + g]);
                uint32_t b1 = __float_as_uint(Vbuf[(size_t)(kb+q+4)*ASD + 8*nt + g]);
                mma_tf32(acc[nt][0], acc[nt][1], acc[nt][2], acc[nt][3],
                         a0, a1, a2, a3, b0, b1);
            }
        }
        __syncthreads();   // all reads of this buffer done before next prefetch
    }

    float inv0 = 1.0f / l0;
    float inv1 = 1.0f / l1;
    float* Ob = O + ((size_t)b*SEQ + (size_t)qt*64) * DMODEL + h*HD;
    #pragma unroll
    for (int nt = 0; nt < 8; nt++) {
        int col = 8*nt + 2*q;
        float2 o0; o0.x = acc[nt][0]*inv0; o0.y = acc[nt][1]*inv0;
        float2 o1; o1.x = acc[nt][2]*inv1; o1.y = acc[nt][3]*inv1;
        *(float2*)(Ob + (size_t)r0 * DMODEL + col) = o0;
        *(float2*)(Ob + (size_t)r1 * DMODEL + col) = o1;
    }
}

// ---------------- launch ----------------
extern "C" void kernel_launch(void* const* d_in, const int* in_sizes, int n_in,
                              void* d_out, int out_size)
{
    const float* x    = (const float*)d_in[0];
    const float* Wq   = (const float*)d_in[1];
    const float* Wk   = (const float*)d_in[2];
    const float* Wv   = (const float*)d_in[3];
    const float* Wo   = (const float*)d_in[4];
    const float* Wup  = (const float*)d_in[5];
    const float* Wdn  = (const float*)d_in[6];
    const float* ln1m = (const float*)d_in[7];
    const float* ln1s = (const float*)d_in[8];
    const float* ln2m = (const float*)d_in[9];
    const float* ln2s = (const float*)d_in[10];
    float* out = (float*)d_out;

    float *b0, *b1, *b2, *b3, *b4, *bm;
    cudaGetSymbolAddress((void**)&b0, g_buf0);
    cudaGetSymbolAddress((void**)&b1, g_buf1);
    cudaGetSymbolAddress((void**)&b2, g_buf2);
    cudaGetSymbolAddress((void**)&b3, g_buf3);
    cudaGetSymbolAddress((void**)&b4, g_buf4);
    cudaGetSymbolAddress((void**)&bm, g_mid);

    const int gemm_smem = 4 * TILE_FLOATS * (int)sizeof(float);  // 73728 B
    cudaFuncSetAttribute(gemm_tc<EPI_NONE>, cudaFuncAttributeMaxDynamicSharedMemorySize, gemm_smem);
    cudaFuncSetAttribute(gemm_tc<EPI_GELU>, cudaFuncAttributeMaxDynamicSharedMemorySize, gemm_smem);
    cudaFuncSetAttribute(gemm_tc<EPI_ADD>,  cudaFuncAttributeMaxDynamicSharedMemorySize, gemm_smem);
    cudaFuncSetAttribute(gemm_qkv,          cudaFuncAttributeMaxDynamicSharedMemorySize, gemm_smem);

    const int attn_smem = 6 * 64 * ASD * (int)sizeof(float);     // 104448 B
    cudaFuncSetAttribute(attn_tc, cudaFuncAttributeMaxDynamicSharedMemorySize, attn_smem);

    dim3 gproj(DMODEL/128, MROWS/128);      // (8, 32)
    dim3 gqkv (DMODEL/128, MROWS/128, 3);   // fused QKV
    dim3 gup  (DFF/128,    MROWS/128);      // (32, 32)

    // LN1
    ln_kernel<<<MROWS, 256>>>(x, ln1m, ln1s, b0);
    // fused QKV
    gemm_qkv<<<gqkv, 256, gemm_smem>>>(b0, Wq, Wk, Wv, b1, b2, b3);
    // tensor-core flash attention (O overwrites b0)
    attn_tc<<<dim3(SEQ/64, NH, BDIM), 128, attn_smem>>>(b1, b2, b3, b0);
    // out proj + residual -> y1
    gemm_tc<EPI_ADD><<<gproj, 256, gemm_smem>>>(b0, Wo, x, b4, MROWS, DMODEL, DMODEL);
    // LN2
    ln_kernel<<<MROWS, 256>>>(b4, ln2m, ln2s, b1);
    // MLP up + GELU
    gemm_tc<EPI_GELU><<<gup, 256, gemm_smem>>>(b1, Wup, nullptr, bm, MROWS, DFF, DMODEL);
    // MLP down + residual -> out
    gemm_tc<EPI_ADD><<<gproj, 256, gemm_smem>>>(bm, Wdn, b4, out, MROWS, DMODEL, DFF);
}